// round 14
// baseline (speedup 1.0000x reference)
#include <cuda_runtime.h>
#include <cuda_fp16.h>
#include <cstdint>
#include <math_constants.h>

#define IN_DIM   128
#define HID      64
#define G_MAX    8192
#define CHUNK    64
#define THREADS  256
#define KP       136        // fp16 row stride: 272 B = 17*16B -> ldmatrix conflict-free
#define MT_STRIDE (16 * KP * 2)   // 4352 B per 16-row tile group
#define XBUF_SZ  17408      // one x buffer: [64 nodes][KP] fp16

// ---- SMEM layout (bytes); tile bases 16B-aligned
#define WH_OFF    0                         // W1^T fp16 [64 n][KP] = 17408
#define XB_OFF    17408                     // x bufs: [buf][64][KP] fp16, x2
#define B1S_OFF   52224                     // 64 f32
#define W2S_OFF   52480                     // 64 f32
#define GP_OFF    52736                     // 2*64 f32 gate partials
#define ES_OFF    53248                     // 64 f32 exp weights
#define ACC2_OFF  53504                     // 3*128 f32 pool quarter-combine
#define RED_OFF   55040                     // 4 f32 (+pad)
#define SMEM_TOTAL 55072                    // x3 CTA = 165 KB <= 228 KB/SM

__device__ int g_seg_start[G_MAX + 1];

// ---------------------------------------------------------------------------
// Kernel 1: segment offsets from sorted batch (int32 view; inline i64 detect).
// ---------------------------------------------------------------------------
__global__ void seg_offsets_kernel(const int* __restrict__ b32, int n, int G)
{
    int i = blockIdx.x * blockDim.x + threadIdx.x;
    if (i > n) return;
    const int s = (b32[(n / 2) | 1] == 0) ? 2 : 1;   // int64 -> stride 2 (low word)
    int cur  = (i < n) ? b32[(size_t)i * s]       : G;
    int prev = (i > 0) ? b32[(size_t)(i - 1) * s] : -1;
    cur  = min(max(cur,  -1), G);
    prev = min(max(prev, -1), G);
    for (int g = prev + 1; g <= cur; ++g)
        g_seg_start[g] = i;
}

// ---------------------------------------------------------------------------
// baseline-feature tensor ops (sm_80+, legal at compute_103)
// ---------------------------------------------------------------------------
__device__ __forceinline__ uint32_t smem_u32(const void* p)
{
    uint32_t a;
    asm("{ .reg .u64 t; cvta.to.shared.u64 t, %1; cvt.u32.u64 %0, t; }"
        : "=r"(a) : "l"(p));
    return a;
}

__device__ __forceinline__ void ldmx4(uint32_t addr, uint32_t* r)
{
    asm volatile("ldmatrix.sync.aligned.m8n8.x4.shared.b16 {%0,%1,%2,%3}, [%4];"
                 : "=r"(r[0]), "=r"(r[1]), "=r"(r[2]), "=r"(r[3]) : "r"(addr));
}

__device__ __forceinline__ void mma16816(float* c, const uint32_t* a,
                                         const uint32_t* b)
{
    asm volatile("mma.sync.aligned.m16n8k16.row.col.f32.f16.f16.f32 "
                 "{%0,%1,%2,%3}, {%4,%5,%6,%7}, {%8,%9}, {%0,%1,%2,%3};"
                 : "+f"(c[0]), "+f"(c[1]), "+f"(c[2]), "+f"(c[3])
                 : "r"(a[0]), "r"(a[1]), "r"(a[2]), "r"(a[3]),
                   "r"(b[0]), "r"(b[1]));
}

__device__ __forceinline__ uint32_t pack_h2(float v0, float v1)
{
    const __half h0 = __float2half_rn(v0);
    const __half h1 = __float2half_rn(v1);
    return ((uint32_t)__half_as_ushort(h1) << 16) |
            (uint32_t)__half_as_ushort(h0);
}

// ---------------------------------------------------------------------------
// Kernel 2: fused gate-MLP (mma.sync fp16) + online softmax (2 barriers) +
// pooling; chunk-level software pipeline, single fp16 x buffer.
// One CTA per graph, 256 threads (8 warps), 3 CTAs/SM.
// Warp (mg 0..3, nq 0..1): nodes 16mg..16mg+15 (m16 tile) x hid 32nq..+31.
// ---------------------------------------------------------------------------
__global__ __launch_bounds__(THREADS, 3)
void attn_pool_kernel(const float* __restrict__ x,
                      const float* __restrict__ W1,
                      const float* __restrict__ b1,
                      const float* __restrict__ W2,
                      const float* __restrict__ b2,
                      float* __restrict__ out)
{
    extern __shared__ char smem[];
    float* b1s  = (float*)(smem + B1S_OFF);
    float* w2s  = (float*)(smem + W2S_OFF);
    float* gps  = (float*)(smem + GP_OFF);
    float* es   = (float*)(smem + ES_OFF);
    float* acc2 = (float*)(smem + ACC2_OFF);
    float* red  = (float*)(smem + RED_OFF);

    const uint32_t sb = smem_u32(smem);

    const int tid  = threadIdx.x;
    const int lane = tid & 31;
    const int wid  = tid >> 5;        // 0..7
    const int mg   = wid & 3;         // m-group: nodes 16mg..16mg+15
    const int nq   = wid >> 2;        // hid half: 32nq..32nq+31
    const int g    = blockIdx.x;

    const int start = g_seg_start[g];
    const int end   = g_seg_start[g + 1];

    // ---- stage W1^T fp16 [n][k] (one-time; col-major B fragment layout)
    for (int e = tid; e < HID * IN_DIM; e += THREADS) {
        const int n = e & (HID - 1);
        const int k = e >> 6;
        *(__half*)(smem + WH_OFF + (n * KP + k) * 2) =
            __float2half_rn(W1[k * HID + n]);
    }
    if (tid < HID) { b1s[tid] = b1[tid]; w2s[tid] = W2[tid]; }
    const float b2v = b2[0];

    // ---- ldmatrix per-lane offsets (fragment math validated R9-R12)
    const uint32_t a_off = (((uint32_t)(lane & 15)) * KP +
                            ((uint32_t)(lane >> 4)) * 8) * 2 +
                           (uint32_t)(mg * 16) * KP * 2;
    const uint32_t b_off = (((uint32_t)((lane & 7) + ((lane >> 4) << 3))) * KP +
                            ((uint32_t)((lane >> 3) & 1)) * 8) * 2;
    const uint32_t bw = sb + WH_OFF + (uint32_t)(nq * 32) * KP * 2 + b_off;

    // load/pool identity: thread = (dp dim-pair 0..63, ph node-quarter 0..3)
    const int dp = tid & 63;
    const int ph = tid >> 6;

    float m_run = -CUDART_INF_F;
    float s_run = 0.f;
    float pacc0 = 0.f, pacc1 = 0.f;

    // ---- prologue: stage chunk 0 into buffer 0 (zero-pad tail)
    if (start < end) {
        const int c0 = min(CHUNK, end - start);
        #pragma unroll 4
        for (int i = 0; i < 16; ++i) {
            const int n = ph * 16 + i;
            float2 v = make_float2(0.f, 0.f);
            if (n < c0)
                v = *((const float2*)(x + (size_t)(start + n) * IN_DIM) + dp);
            *(uint32_t*)(smem + XB_OFF + n * (KP * 2) + dp * 4) = pack_h2(v.x, v.y);
        }
    }
    __syncthreads();

    for (int cs = start, p = 0; cs < end; cs += CHUNK, p ^= 1) {
        const int c   = min(CHUNK, end - cs);
        const int cs2 = cs + CHUNK;
        const bool hn = cs2 < end;
        const int c2  = hn ? min(CHUNK, end - cs2) : 0;

        // ---- prefetch next chunk, convert to fp16 in regs (16 u32)
        uint32_t v[16];
        if (hn) {
            #pragma unroll
            for (int i = 0; i < 16; ++i) {
                const int n = ph * 16 + i;
                float2 f = make_float2(0.f, 0.f);
                if (n < c2)
                    f = *((const float2*)(x + (size_t)(cs2 + n) * IN_DIM) + dp);
                v[i] = pack_h2(f.x, f.y);
            }
        }

        // ---- MMA: warp computes D[16 x 32] = x[16 x 128] @ W1[128 x 32]
        {
            const uint32_t ax = sb + XB_OFF + (uint32_t)p * XBUF_SZ + a_off;

            float acc[4][4];
            #pragma unroll
            for (int nt = 0; nt < 4; ++nt)
                #pragma unroll
                for (int q = 0; q < 4; ++q) acc[nt][q] = 0.f;

            #pragma unroll 1
            for (int ks = 0; ks < 8; ++ks) {
                const uint32_t kb = (uint32_t)ks * 32;   // 16 fp16 = 32 B
                uint32_t ah[4], bh[2][4];
                ldmx4(ax + kb, ah);
                #pragma unroll
                for (int np = 0; np < 2; ++np)
                    ldmx4(bw + (uint32_t)np * MT_STRIDE + kb, bh[np]);
                #pragma unroll
                for (int np = 0; np < 2; ++np) {
                    mma16816(acc[2 * np],     ah, bh[np]);
                    mma16816(acc[2 * np + 1], ah, bh[np] + 2);
                }
            }

            // epilogue: relu + W2 partial (this hid half), quad-reduce
            float gp0 = 0.f, gp1 = 0.f;   // rows (lane>>2), (lane>>2)+8
            #pragma unroll
            for (int nt = 0; nt < 4; ++nt) {
                const int j0 = nq * 32 + nt * 8 + (lane & 3) * 2;
                const float bj0 = b1s[j0], bj1 = b1s[j0 + 1];
                const float wj0 = w2s[j0], wj1 = w2s[j0 + 1];
                gp0 = fmaf(fmaxf(acc[nt][0] + bj0, 0.f), wj0, gp0);
                gp0 = fmaf(fmaxf(acc[nt][1] + bj1, 0.f), wj1, gp0);
                gp1 = fmaf(fmaxf(acc[nt][2] + bj0, 0.f), wj0, gp1);
                gp1 = fmaf(fmaxf(acc[nt][3] + bj1, 0.f), wj1, gp1);
            }
            #pragma unroll
            for (int off = 1; off < 4; off <<= 1) {
                gp0 += __shfl_xor_sync(0xffffffffu, gp0, off);
                gp1 += __shfl_xor_sync(0xffffffffu, gp1, off);
            }
            if ((lane & 3) == 0) {
                const int node = mg * 16 + (lane >> 2);
                gps[nq * 64 + node]     = gp0;
                gps[nq * 64 + node + 8] = gp1;
            }
        }
        __syncthreads();   // BAR 1: gps ready; prev pooling/es reads done

        // ---- warps 0-1: per-warp softmax partials (no inner barrier)
        if (tid < CHUNK) {
            const float gate = (tid < c) ? (gps[tid] + gps[64 + tid] + b2v)
                                         : -CUDART_INF_F;
            float mw = gate;
            #pragma unroll
            for (int o = 16; o; o >>= 1)
                mw = fmaxf(mw, __shfl_xor_sync(0xffffffffu, mw, o));
            const float mws = fmaxf(mw, -1e30f);   // all-masked warp -> finite
            const float e = expf(gate - mws);      // masked: exp(-inf) = 0
            es[tid] = e;
            float sw = e;
            #pragma unroll
            for (int o = 16; o; o >>= 1)
                sw += __shfl_xor_sync(0xffffffffu, sw, o);
            if (lane == 0) { red[2 * wid] = mws; red[2 * wid + 1] = sw; }
        }

        // ---- all threads: store prefetched chunk into other buffer
        if (hn) {
            char* xb = smem + XB_OFF + (p ^ 1) * XBUF_SZ;
            #pragma unroll
            for (int i = 0; i < 16; ++i) {
                const int n = ph * 16 + i;
                *(uint32_t*)(xb + n * (KP * 2) + dp * 4) = v[i];
            }
        }
        __syncthreads();   // BAR 2: red + es ready; next buffer staged

        // ---- combine the two warp partials analytically (all threads)
        const float m0 = red[0], s0 = red[1], m1 = red[2], s1 = red[3];
        const float m_new = fmaxf(m_run, fmaxf(m0, m1));
        const float resc  = expf(m_run - m_new);   // first chunk: 0
        const float sc0   = expf(m0 - m_new);
        const float sc1   = expf(m1 - m_new);
        s_run = s_run * resc + fmaf(s0, sc0, s1 * sc1);
        m_run = m_new;

        // ---- pooling from buffer p: thread (dp, ph), dims 2dp & 2dp+1
        pacc0 *= resc;
        pacc1 *= resc;
        {
            const float scp = (ph < 2) ? sc0 : sc1;   // node-half scale
            const char* xb = smem + XB_OFF + p * XBUF_SZ;
            #pragma unroll 4
            for (int i = 0; i < 16; ++i) {
                const int n = ph * 16 + i;
                const float ev = es[n] * scp;          // warp-broadcast LDS
                const uint32_t h2 = *(const uint32_t*)(xb + n * (KP * 2) + dp * 4);
                const float v0 =
                    __half2float(__ushort_as_half((unsigned short)(h2 & 0xffff)));
                const float v1 =
                    __half2float(__ushort_as_half((unsigned short)(h2 >> 16)));
                pacc0 = fmaf(ev, v0, pacc0);
                pacc1 = fmaf(ev, v1, pacc1);
            }
        }
    }

    // ---- combine node-quarter partials, write out
    __syncthreads();
    if (ph > 0) {
        acc2[(ph - 1) * IN_DIM + 2 * dp]     = pacc0;
        acc2[(ph - 1) * IN_DIM + 2 * dp + 1] = pacc1;
    }
    __syncthreads();
    if (ph == 0) {
        float2 o2 = make_float2(0.f, 0.f);
        if (end > start) {
            float s0 = pacc0, s1 = pacc1;
            #pragma unroll
            for (int q = 0; q < 3; ++q) {
                s0 += acc2[q * IN_DIM + 2 * dp];
                s1 += acc2[q * IN_DIM + 2 * dp + 1];
            }
            o2.x = s0 / s_run;
            o2.y = s1 / s_run;
        }
        *((float2*)(out + (size_t)g * IN_DIM) + dp) = o2;
    }
}

// ---------------------------------------------------------------------------
extern "C" void kernel_launch(void* const* d_in, const int* in_sizes, int n_in,
                              void* d_out, int out_size)
{
    const float* x   = (const float*)d_in[0];
    const int*   b32 = (const int*)d_in[1];   // int32 view: safe for i32/i64
    const float* W1  = (const float*)d_in[2];
    const float* b1  = (const float*)d_in[3];
    const float* W2  = (const float*)d_in[4];
    const float* b2  = (const float*)d_in[5];
    float*       out = (float*)d_out;

    const int N = in_sizes[0] / IN_DIM;
    int G = out_size / IN_DIM;
    if (G > G_MAX) G = G_MAX;

    seg_offsets_kernel<<<(N + 1 + 255) / 256, 256>>>(b32, N, G);

    cudaFuncSetAttribute(attn_pool_kernel,
                         cudaFuncAttributeMaxDynamicSharedMemorySize, SMEM_TOTAL);
    attn_pool_kernel<<<G, THREADS, SMEM_TOTAL>>>(x, W1, b1, W2, b2, out);
}

// round 15
// speedup vs baseline: 1.0026x; 1.0026x over previous
#include <cuda_runtime.h>
#include <cuda_fp16.h>
#include <cstdint>
#include <math_constants.h>

#define IN_DIM   128
#define HID      64
#define G_MAX    8192
#define CHUNK    64
#define THREADS  256
#define KP       136        // fp16 row stride: 272 B = 17*16B -> ldmatrix conflict-free
#define MT_STRIDE (16 * KP * 2)   // 4352 B per 16-row tile group
#define XBUF_SZ  17408      // one x buffer: [64 nodes][KP] fp16

// ---- SMEM layout (bytes); tile bases 16B-aligned
#define WH_OFF    0                         // W1^T fp16 [64 n][KP] = 17408
#define XB_OFF    17408                     // x bufs: [buf][64][KP] fp16, x2
#define B1S_OFF   52224                     // 64 f32
#define W2S_OFF   52480                     // 64 f32
#define GP_OFF    52736                     // 2*64 f32 gate partials
#define ES_OFF    53248                     // 64 f32 exp weights
#define ACC2_OFF  53504                     // 3*128 f32 pool quarter-combine
#define RED_OFF   55040                     // 4 f32 (+pad)
#define SMEM_TOTAL 55072                    // x3 CTA = 165 KB <= 228 KB/SM

__device__ int g_seg_start[G_MAX + 1];

// ---------------------------------------------------------------------------
// Kernel 1: segment offsets from sorted batch (int32 view; inline i64 detect).
// ---------------------------------------------------------------------------
__global__ void seg_offsets_kernel(const int* __restrict__ b32, int n, int G)
{
    int i = blockIdx.x * blockDim.x + threadIdx.x;
    if (i > n) return;
    const int s = (b32[(n / 2) | 1] == 0) ? 2 : 1;   // int64 -> stride 2 (low word)
    int cur  = (i < n) ? b32[(size_t)i * s]       : G;
    int prev = (i > 0) ? b32[(size_t)(i - 1) * s] : -1;
    cur  = min(max(cur,  -1), G);
    prev = min(max(prev, -1), G);
    for (int g = prev + 1; g <= cur; ++g)
        g_seg_start[g] = i;
}

// ---------------------------------------------------------------------------
// baseline-feature tensor ops (sm_80+, legal at compute_103)
// ---------------------------------------------------------------------------
__device__ __forceinline__ uint32_t smem_u32(const void* p)
{
    uint32_t a;
    asm("{ .reg .u64 t; cvta.to.shared.u64 t, %1; cvt.u32.u64 %0, t; }"
        : "=r"(a) : "l"(p));
    return a;
}

__device__ __forceinline__ void ldmx4(uint32_t addr, uint32_t* r)
{
    asm volatile("ldmatrix.sync.aligned.m8n8.x4.shared.b16 {%0,%1,%2,%3}, [%4];"
                 : "=r"(r[0]), "=r"(r[1]), "=r"(r[2]), "=r"(r[3]) : "r"(addr));
}

__device__ __forceinline__ void mma16816(float* c, const uint32_t* a,
                                         const uint32_t* b)
{
    asm volatile("mma.sync.aligned.m16n8k16.row.col.f32.f16.f16.f32 "
                 "{%0,%1,%2,%3}, {%4,%5,%6,%7}, {%8,%9}, {%0,%1,%2,%3};"
                 : "+f"(c[0]), "+f"(c[1]), "+f"(c[2]), "+f"(c[3])
                 : "r"(a[0]), "r"(a[1]), "r"(a[2]), "r"(a[3]),
                   "r"(b[0]), "r"(b[1]));
}

__device__ __forceinline__ uint32_t pack_h2(float v0, float v1)
{
    const __half h0 = __float2half_rn(v0);
    const __half h1 = __float2half_rn(v1);
    return ((uint32_t)__half_as_ushort(h1) << 16) |
            (uint32_t)__half_as_ushort(h0);
}

// ---------------------------------------------------------------------------
// Kernel 2: fused gate-MLP (mma.sync fp16) + online softmax (2 barriers) +
// pooling; chunk-level software pipeline, single fp16 x buffer.
// One CTA per graph, 256 threads (8 warps), 3 CTAs/SM.
// Warp (mg 0..3, nq 0..1): nodes 16mg..16mg+15 (m16 tile) x hid 32nq..+31.
// ---------------------------------------------------------------------------
__global__ __launch_bounds__(THREADS, 3)
void attn_pool_kernel(const float* __restrict__ x,
                      const float* __restrict__ W1,
                      const float* __restrict__ b1,
                      const float* __restrict__ W2,
                      const float* __restrict__ b2,
                      float* __restrict__ out)
{
    extern __shared__ char smem[];
    float* b1s  = (float*)(smem + B1S_OFF);
    float* w2s  = (float*)(smem + W2S_OFF);
    float* gps  = (float*)(smem + GP_OFF);
    float* es   = (float*)(smem + ES_OFF);
    float* acc2 = (float*)(smem + ACC2_OFF);
    float* red  = (float*)(smem + RED_OFF);

    const uint32_t sb = smem_u32(smem);

    const int tid  = threadIdx.x;
    const int lane = tid & 31;
    const int wid  = tid >> 5;        // 0..7
    const int mg   = wid & 3;         // m-group: nodes 16mg..16mg+15
    const int nq   = wid >> 2;        // hid half: 32nq..32nq+31
    const int g    = blockIdx.x;

    const int start = g_seg_start[g];
    const int end   = g_seg_start[g + 1];

    // ---- stage W1^T fp16 [n][k] (one-time; col-major B fragment layout)
    for (int e = tid; e < HID * IN_DIM; e += THREADS) {
        const int n = e & (HID - 1);
        const int k = e >> 6;
        *(__half*)(smem + WH_OFF + (n * KP + k) * 2) =
            __float2half_rn(W1[k * HID + n]);
    }
    if (tid < HID) { b1s[tid] = b1[tid]; w2s[tid] = W2[tid]; }
    const float b2v = b2[0];

    // ---- ldmatrix per-lane offsets (fragment math validated R9-R12)
    const uint32_t a_off = (((uint32_t)(lane & 15)) * KP +
                            ((uint32_t)(lane >> 4)) * 8) * 2 +
                           (uint32_t)(mg * 16) * KP * 2;
    const uint32_t b_off = (((uint32_t)((lane & 7) + ((lane >> 4) << 3))) * KP +
                            ((uint32_t)((lane >> 3) & 1)) * 8) * 2;
    const uint32_t bw = sb + WH_OFF + (uint32_t)(nq * 32) * KP * 2 + b_off;

    // load/pool identity: thread = (dp dim-pair 0..63, ph node-quarter 0..3)
    const int dp = tid & 63;
    const int ph = tid >> 6;

    float m_run = -CUDART_INF_F;
    float s_run = 0.f;
    float pacc0 = 0.f, pacc1 = 0.f;

    // ---- prologue: stage chunk 0 into buffer 0 (zero-pad tail)
    if (start < end) {
        const int c0 = min(CHUNK, end - start);
        #pragma unroll 4
        for (int i = 0; i < 16; ++i) {
            const int n = ph * 16 + i;
            float2 v = make_float2(0.f, 0.f);
            if (n < c0)
                v = *((const float2*)(x + (size_t)(start + n) * IN_DIM) + dp);
            *(uint32_t*)(smem + XB_OFF + n * (KP * 2) + dp * 4) = pack_h2(v.x, v.y);
        }
    }
    __syncthreads();

    for (int cs = start, p = 0; cs < end; cs += CHUNK, p ^= 1) {
        const int c   = min(CHUNK, end - cs);
        const int cs2 = cs + CHUNK;
        const bool hn = cs2 < end;
        const int c2  = hn ? min(CHUNK, end - cs2) : 0;

        // ---- prefetch next chunk, convert to fp16 in regs (16 u32)
        uint32_t v[16];
        if (hn) {
            #pragma unroll
            for (int i = 0; i < 16; ++i) {
                const int n = ph * 16 + i;
                float2 f = make_float2(0.f, 0.f);
                if (n < c2)
                    f = *((const float2*)(x + (size_t)(cs2 + n) * IN_DIM) + dp);
                v[i] = pack_h2(f.x, f.y);
            }
        }

        // ---- MMA: warp computes D[16 x 32] = x[16 x 128] @ W1[128 x 32]
        {
            const uint32_t ax = sb + XB_OFF + (uint32_t)p * XBUF_SZ + a_off;

            float acc[4][4];
            #pragma unroll
            for (int nt = 0; nt < 4; ++nt)
                #pragma unroll
                for (int q = 0; q < 4; ++q) acc[nt][q] = 0.f;

            #pragma unroll 1
            for (int ks = 0; ks < 8; ++ks) {
                const uint32_t kb = (uint32_t)ks * 32;   // 16 fp16 = 32 B
                uint32_t ah[4], bh[2][4];
                ldmx4(ax + kb, ah);
                #pragma unroll
                for (int np = 0; np < 2; ++np)
                    ldmx4(bw + (uint32_t)np * MT_STRIDE + kb, bh[np]);
                #pragma unroll
                for (int np = 0; np < 2; ++np) {
                    mma16816(acc[2 * np],     ah, bh[np]);
                    mma16816(acc[2 * np + 1], ah, bh[np] + 2);
                }
            }

            // epilogue: relu + W2 partial (this hid half), quad-reduce
            float gp0 = 0.f, gp1 = 0.f;   // rows (lane>>2), (lane>>2)+8
            #pragma unroll
            for (int nt = 0; nt < 4; ++nt) {
                const int j0 = nq * 32 + nt * 8 + (lane & 3) * 2;
                const float bj0 = b1s[j0], bj1 = b1s[j0 + 1];
                const float wj0 = w2s[j0], wj1 = w2s[j0 + 1];
                gp0 = fmaf(fmaxf(acc[nt][0] + bj0, 0.f), wj0, gp0);
                gp0 = fmaf(fmaxf(acc[nt][1] + bj1, 0.f), wj1, gp0);
                gp1 = fmaf(fmaxf(acc[nt][2] + bj0, 0.f), wj0, gp1);
                gp1 = fmaf(fmaxf(acc[nt][3] + bj1, 0.f), wj1, gp1);
            }
            #pragma unroll
            for (int off = 1; off < 4; off <<= 1) {
                gp0 += __shfl_xor_sync(0xffffffffu, gp0, off);
                gp1 += __shfl_xor_sync(0xffffffffu, gp1, off);
            }
            if ((lane & 3) == 0) {
                const int node = mg * 16 + (lane >> 2);
                gps[nq * 64 + node]     = gp0;
                gps[nq * 64 + node + 8] = gp1;
            }
        }
        __syncthreads();   // BAR 1: gps ready; prev pooling/es reads done

        // ---- warps 0-1: per-warp softmax partials (no inner barrier)
        if (tid < CHUNK) {
            const float gate = (tid < c) ? (gps[tid] + gps[64 + tid] + b2v)
                                         : -CUDART_INF_F;
            float mw = gate;
            #pragma unroll
            for (int o = 16; o; o >>= 1)
                mw = fmaxf(mw, __shfl_xor_sync(0xffffffffu, mw, o));
            const float mws = fmaxf(mw, -1e30f);   // all-masked warp -> finite
            const float e = expf(gate - mws);      // masked: exp(-inf) = 0
            es[tid] = e;
            float sw = e;
            #pragma unroll
            for (int o = 16; o; o >>= 1)
                sw += __shfl_xor_sync(0xffffffffu, sw, o);
            if (lane == 0) { red[2 * wid] = mws; red[2 * wid + 1] = sw; }
        }

        // ---- all threads: store prefetched chunk into other buffer
        if (hn) {
            char* xb = smem + XB_OFF + (p ^ 1) * XBUF_SZ;
            #pragma unroll
            for (int i = 0; i < 16; ++i) {
                const int n = ph * 16 + i;
                *(uint32_t*)(xb + n * (KP * 2) + dp * 4) = v[i];
            }
        }
        __syncthreads();   // BAR 2: red + es ready; next buffer staged

        // ---- combine the two warp partials analytically (all threads)
        const float m0 = red[0], s0 = red[1], m1 = red[2], s1 = red[3];
        const float m_new = fmaxf(m_run, fmaxf(m0, m1));
        const float resc  = expf(m_run - m_new);   // first chunk: 0
        const float sc0   = expf(m0 - m_new);
        const float sc1   = expf(m1 - m_new);
        s_run = s_run * resc + fmaf(s0, sc0, s1 * sc1);
        m_run = m_new;

        // ---- pooling from buffer p: thread (dp, ph), dims 2dp & 2dp+1
        pacc0 *= resc;
        pacc1 *= resc;
        {
            const float scp = (ph < 2) ? sc0 : sc1;   // node-half scale
            const char* xb = smem + XB_OFF + p * XBUF_SZ;
            #pragma unroll 4
            for (int i = 0; i < 16; ++i) {
                const int n = ph * 16 + i;
                const float ev = es[n] * scp;          // warp-broadcast LDS
                const uint32_t h2 = *(const uint32_t*)(xb + n * (KP * 2) + dp * 4);
                const float v0 =
                    __half2float(__ushort_as_half((unsigned short)(h2 & 0xffff)));
                const float v1 =
                    __half2float(__ushort_as_half((unsigned short)(h2 >> 16)));
                pacc0 = fmaf(ev, v0, pacc0);
                pacc1 = fmaf(ev, v1, pacc1);
            }
        }
    }

    // ---- combine node-quarter partials, write out
    __syncthreads();
    if (ph > 0) {
        acc2[(ph - 1) * IN_DIM + 2 * dp]     = pacc0;
        acc2[(ph - 1) * IN_DIM + 2 * dp + 1] = pacc1;
    }
    __syncthreads();
    if (ph == 0) {
        float2 o2 = make_float2(0.f, 0.f);
        if (end > start) {
            float s0 = pacc0, s1 = pacc1;
            #pragma unroll
            for (int q = 0; q < 3; ++q) {
                s0 += acc2[q * IN_DIM + 2 * dp];
                s1 += acc2[q * IN_DIM + 2 * dp + 1];
            }
            o2.x = s0 / s_run;
            o2.y = s1 / s_run;
        }
        *((float2*)(out + (size_t)g * IN_DIM) + dp) = o2;
    }
}

// ---------------------------------------------------------------------------
extern "C" void kernel_launch(void* const* d_in, const int* in_sizes, int n_in,
                              void* d_out, int out_size)
{
    const float* x   = (const float*)d_in[0];
    const int*   b32 = (const int*)d_in[1];   // int32 view: safe for i32/i64
    const float* W1  = (const float*)d_in[2];
    const float* b1  = (const float*)d_in[3];
    const float* W2  = (const float*)d_in[4];
    const float* b2  = (const float*)d_in[5];
    float*       out = (float*)d_out;

    const int N = in_sizes[0] / IN_DIM;
    int G = out_size / IN_DIM;
    if (G > G_MAX) G = G_MAX;

    seg_offsets_kernel<<<(N + 1 + 255) / 256, 256>>>(b32, N, G);

    cudaFuncSetAttribute(attn_pool_kernel,
                         cudaFuncAttributeMaxDynamicSharedMemorySize, SMEM_TOTAL);
    attn_pool_kernel<<<G, THREADS, SMEM_TOTAL>>>(x, W1, b1, W2, b2, out);
}

// round 16
// speedup vs baseline: 1.0062x; 1.0035x over previous
#include <cuda_runtime.h>
#include <cuda_fp16.h>
#include <cstdint>
#include <math_constants.h>

#define IN_DIM   128
#define HID      64
#define G_MAX    8192
#define CHUNK    64
#define THREADS  256
#define KP       136        // fp16 row stride: 272 B = 17*16B -> ldmatrix conflict-free
#define MT_STRIDE (16 * KP * 2)   // 4352 B per 16-row tile group
#define XBUF_SZ  17408      // one x buffer: [64 nodes][KP] fp16

// ---- SMEM layout (bytes); tile bases 16B-aligned
#define WH_OFF    0                         // W1^T fp16 [64 n][KP] = 17408
#define XB_OFF    17408                     // x bufs: [buf][64][KP] fp16, x2
#define B1S_OFF   52224                     // 64 f32
#define W2S_OFF   52480                     // 64 f32
#define GP_OFF    52736                     // 2*64 f32 gate partials
#define ES_OFF    53248                     // 64 f32 exp weights
#define ACC2_OFF  53504                     // 3*128 f32 pool quarter-combine
#define RED_OFF   55040                     // 4 f32 (+pad)
#define SMEM_TOTAL 55072                    // x3 CTA = 165 KB <= 228 KB/SM

__device__ int g_seg_start[G_MAX + 1];

// ---------------------------------------------------------------------------
// Kernel 1: segment offsets from sorted batch (int32 view; inline i64 detect).
// ---------------------------------------------------------------------------
__global__ void seg_offsets_kernel(const int* __restrict__ b32, int n, int G)
{
    int i = blockIdx.x * blockDim.x + threadIdx.x;
    if (i > n) return;
    const int s = (b32[(n / 2) | 1] == 0) ? 2 : 1;   // int64 -> stride 2 (low word)
    int cur  = (i < n) ? b32[(size_t)i * s]       : G;
    int prev = (i > 0) ? b32[(size_t)(i - 1) * s] : -1;
    cur  = min(max(cur,  -1), G);
    prev = min(max(prev, -1), G);
    for (int g = prev + 1; g <= cur; ++g)
        g_seg_start[g] = i;
}

// ---------------------------------------------------------------------------
// baseline-feature tensor ops (sm_80+, legal at compute_103)
// ---------------------------------------------------------------------------
__device__ __forceinline__ uint32_t smem_u32(const void* p)
{
    uint32_t a;
    asm("{ .reg .u64 t; cvta.to.shared.u64 t, %1; cvt.u32.u64 %0, t; }"
        : "=r"(a) : "l"(p));
    return a;
}

__device__ __forceinline__ void ldmx4(uint32_t addr, uint32_t* r)
{
    asm volatile("ldmatrix.sync.aligned.m8n8.x4.shared.b16 {%0,%1,%2,%3}, [%4];"
                 : "=r"(r[0]), "=r"(r[1]), "=r"(r[2]), "=r"(r[3]) : "r"(addr));
}

__device__ __forceinline__ void mma16816(float* c, const uint32_t* a,
                                         const uint32_t* b)
{
    asm volatile("mma.sync.aligned.m16n8k16.row.col.f32.f16.f16.f32 "
                 "{%0,%1,%2,%3}, {%4,%5,%6,%7}, {%8,%9}, {%0,%1,%2,%3};"
                 : "+f"(c[0]), "+f"(c[1]), "+f"(c[2]), "+f"(c[3])
                 : "r"(a[0]), "r"(a[1]), "r"(a[2]), "r"(a[3]),
                   "r"(b[0]), "r"(b[1]));
}

__device__ __forceinline__ uint32_t pack_h2(float v0, float v1)
{
    const __half h0 = __float2half_rn(v0);
    const __half h1 = __float2half_rn(v1);
    return ((uint32_t)__half_as_ushort(h1) << 16) |
            (uint32_t)__half_as_ushort(h0);
}

// ---------------------------------------------------------------------------
// Kernel 2: fused gate-MLP (mma.sync fp16) + online softmax (2 barriers) +
// pooling; chunk-level software pipeline, single fp16 x buffer.
// One CTA per graph, 256 threads (8 warps), 3 CTAs/SM.
// Warp (mg 0..3, nq 0..1): nodes 16mg..16mg+15 (m16 tile) x hid 32nq..+31.
// ---------------------------------------------------------------------------
__global__ __launch_bounds__(THREADS, 3)
void attn_pool_kernel(const float* __restrict__ x,
                      const float* __restrict__ W1,
                      const float* __restrict__ b1,
                      const float* __restrict__ W2,
                      const float* __restrict__ b2,
                      float* __restrict__ out)
{
    extern __shared__ char smem[];
    float* b1s  = (float*)(smem + B1S_OFF);
    float* w2s  = (float*)(smem + W2S_OFF);
    float* gps  = (float*)(smem + GP_OFF);
    float* es   = (float*)(smem + ES_OFF);
    float* acc2 = (float*)(smem + ACC2_OFF);
    float* red  = (float*)(smem + RED_OFF);

    const uint32_t sb = smem_u32(smem);

    const int tid  = threadIdx.x;
    const int lane = tid & 31;
    const int wid  = tid >> 5;        // 0..7
    const int mg   = wid & 3;         // m-group: nodes 16mg..16mg+15
    const int nq   = wid >> 2;        // hid half: 32nq..32nq+31
    const int g    = blockIdx.x;

    const int start = g_seg_start[g];
    const int end   = g_seg_start[g + 1];

    // ---- stage W1^T fp16 [n][k] (one-time; col-major B fragment layout)
    for (int e = tid; e < HID * IN_DIM; e += THREADS) {
        const int n = e & (HID - 1);
        const int k = e >> 6;
        *(__half*)(smem + WH_OFF + (n * KP + k) * 2) =
            __float2half_rn(W1[k * HID + n]);
    }
    if (tid < HID) { b1s[tid] = b1[tid]; w2s[tid] = W2[tid]; }
    const float b2v = b2[0];

    // ---- ldmatrix per-lane offsets (fragment math validated R9-R12)
    const uint32_t a_off = (((uint32_t)(lane & 15)) * KP +
                            ((uint32_t)(lane >> 4)) * 8) * 2 +
                           (uint32_t)(mg * 16) * KP * 2;
    const uint32_t b_off = (((uint32_t)((lane & 7) + ((lane >> 4) << 3))) * KP +
                            ((uint32_t)((lane >> 3) & 1)) * 8) * 2;
    const uint32_t bw = sb + WH_OFF + (uint32_t)(nq * 32) * KP * 2 + b_off;

    // load/pool identity: thread = (dp dim-pair 0..63, ph node-quarter 0..3)
    const int dp = tid & 63;
    const int ph = tid >> 6;

    float m_run = -CUDART_INF_F;
    float s_run = 0.f;
    float pacc0 = 0.f, pacc1 = 0.f;

    // ---- prologue: stage chunk 0 into buffer 0 (zero-pad tail)
    if (start < end) {
        const int c0 = min(CHUNK, end - start);
        #pragma unroll 4
        for (int i = 0; i < 16; ++i) {
            const int n = ph * 16 + i;
            float2 v = make_float2(0.f, 0.f);
            if (n < c0)
                v = *((const float2*)(x + (size_t)(start + n) * IN_DIM) + dp);
            *(uint32_t*)(smem + XB_OFF + n * (KP * 2) + dp * 4) = pack_h2(v.x, v.y);
        }
    }
    __syncthreads();

    for (int cs = start, p = 0; cs < end; cs += CHUNK, p ^= 1) {
        const int c   = min(CHUNK, end - cs);
        const int cs2 = cs + CHUNK;
        const bool hn = cs2 < end;
        const int c2  = hn ? min(CHUNK, end - cs2) : 0;

        // ---- prefetch next chunk, convert to fp16 in regs (16 u32)
        uint32_t v[16];
        if (hn) {
            #pragma unroll
            for (int i = 0; i < 16; ++i) {
                const int n = ph * 16 + i;
                float2 f = make_float2(0.f, 0.f);
                if (n < c2)
                    f = *((const float2*)(x + (size_t)(cs2 + n) * IN_DIM) + dp);
                v[i] = pack_h2(f.x, f.y);
            }
        }

        // ---- MMA: warp computes D[16 x 32] = x[16 x 128] @ W1[128 x 32]
        {
            const uint32_t ax = sb + XB_OFF + (uint32_t)p * XBUF_SZ + a_off;

            float acc[4][4];
            #pragma unroll
            for (int nt = 0; nt < 4; ++nt)
                #pragma unroll
                for (int q = 0; q < 4; ++q) acc[nt][q] = 0.f;

            #pragma unroll 1
            for (int ks = 0; ks < 8; ++ks) {
                const uint32_t kb = (uint32_t)ks * 32;   // 16 fp16 = 32 B
                uint32_t ah[4], bh[2][4];
                ldmx4(ax + kb, ah);
                #pragma unroll
                for (int np = 0; np < 2; ++np)
                    ldmx4(bw + (uint32_t)np * MT_STRIDE + kb, bh[np]);
                #pragma unroll
                for (int np = 0; np < 2; ++np) {
                    mma16816(acc[2 * np],     ah, bh[np]);
                    mma16816(acc[2 * np + 1], ah, bh[np] + 2);
                }
            }

            // epilogue: relu + W2 partial (this hid half), quad-reduce
            float gp0 = 0.f, gp1 = 0.f;   // rows (lane>>2), (lane>>2)+8
            #pragma unroll
            for (int nt = 0; nt < 4; ++nt) {
                const int j0 = nq * 32 + nt * 8 + (lane & 3) * 2;
                const float bj0 = b1s[j0], bj1 = b1s[j0 + 1];
                const float wj0 = w2s[j0], wj1 = w2s[j0 + 1];
                gp0 = fmaf(fmaxf(acc[nt][0] + bj0, 0.f), wj0, gp0);
                gp0 = fmaf(fmaxf(acc[nt][1] + bj1, 0.f), wj1, gp0);
                gp1 = fmaf(fmaxf(acc[nt][2] + bj0, 0.f), wj0, gp1);
                gp1 = fmaf(fmaxf(acc[nt][3] + bj1, 0.f), wj1, gp1);
            }
            #pragma unroll
            for (int off = 1; off < 4; off <<= 1) {
                gp0 += __shfl_xor_sync(0xffffffffu, gp0, off);
                gp1 += __shfl_xor_sync(0xffffffffu, gp1, off);
            }
            if ((lane & 3) == 0) {
                const int node = mg * 16 + (lane >> 2);
                gps[nq * 64 + node]     = gp0;
                gps[nq * 64 + node + 8] = gp1;
            }
        }
        __syncthreads();   // BAR 1: gps ready; prev pooling/es reads done

        // ---- warps 0-1: per-warp softmax partials (no inner barrier)
        if (tid < CHUNK) {
            const float gate = (tid < c) ? (gps[tid] + gps[64 + tid] + b2v)
                                         : -CUDART_INF_F;
            float mw = gate;
            #pragma unroll
            for (int o = 16; o; o >>= 1)
                mw = fmaxf(mw, __shfl_xor_sync(0xffffffffu, mw, o));
            const float mws = fmaxf(mw, -1e30f);   // all-masked warp -> finite
            const float e = expf(gate - mws);      // masked: exp(-inf) = 0
            es[tid] = e;
            float sw = e;
            #pragma unroll
            for (int o = 16; o; o >>= 1)
                sw += __shfl_xor_sync(0xffffffffu, sw, o);
            if (lane == 0) { red[2 * wid] = mws; red[2 * wid + 1] = sw; }
        }

        // ---- all threads: store prefetched chunk into other buffer
        if (hn) {
            char* xb = smem + XB_OFF + (p ^ 1) * XBUF_SZ;
            #pragma unroll
            for (int i = 0; i < 16; ++i) {
                const int n = ph * 16 + i;
                *(uint32_t*)(xb + n * (KP * 2) + dp * 4) = v[i];
            }
        }
        __syncthreads();   // BAR 2: red + es ready; next buffer staged

        // ---- combine the two warp partials analytically (all threads)
        const float m0 = red[0], s0 = red[1], m1 = red[2], s1 = red[3];
        const float m_new = fmaxf(m_run, fmaxf(m0, m1));
        const float resc  = expf(m_run - m_new);   // first chunk: 0
        const float sc0   = expf(m0 - m_new);
        const float sc1   = expf(m1 - m_new);
        s_run = s_run * resc + fmaf(s0, sc0, s1 * sc1);
        m_run = m_new;

        // ---- pooling from buffer p: thread (dp, ph), dims 2dp & 2dp+1
        pacc0 *= resc;
        pacc1 *= resc;
        {
            const float scp = (ph < 2) ? sc0 : sc1;   // node-half scale
            const char* xb = smem + XB_OFF + p * XBUF_SZ;
            #pragma unroll 4
            for (int i = 0; i < 16; ++i) {
                const int n = ph * 16 + i;
                const float ev = es[n] * scp;          // warp-broadcast LDS
                const uint32_t h2 = *(const uint32_t*)(xb + n * (KP * 2) + dp * 4);
                const float v0 =
                    __half2float(__ushort_as_half((unsigned short)(h2 & 0xffff)));
                const float v1 =
                    __half2float(__ushort_as_half((unsigned short)(h2 >> 16)));
                pacc0 = fmaf(ev, v0, pacc0);
                pacc1 = fmaf(ev, v1, pacc1);
            }
        }
    }

    // ---- combine node-quarter partials, write out
    __syncthreads();
    if (ph > 0) {
        acc2[(ph - 1) * IN_DIM + 2 * dp]     = pacc0;
        acc2[(ph - 1) * IN_DIM + 2 * dp + 1] = pacc1;
    }
    __syncthreads();
    if (ph == 0) {
        float2 o2 = make_float2(0.f, 0.f);
        if (end > start) {
            float s0 = pacc0, s1 = pacc1;
            #pragma unroll
            for (int q = 0; q < 3; ++q) {
                s0 += acc2[q * IN_DIM + 2 * dp];
                s1 += acc2[q * IN_DIM + 2 * dp + 1];
            }
            o2.x = s0 / s_run;
            o2.y = s1 / s_run;
        }
        *((float2*)(out + (size_t)g * IN_DIM) + dp) = o2;
    }
}

// ---------------------------------------------------------------------------
extern "C" void kernel_launch(void* const* d_in, const int* in_sizes, int n_in,
                              void* d_out, int out_size)
{
    const float* x   = (const float*)d_in[0];
    const int*   b32 = (const int*)d_in[1];   // int32 view: safe for i32/i64
    const float* W1  = (const float*)d_in[2];
    const float* b1  = (const float*)d_in[3];
    const float* W2  = (const float*)d_in[4];
    const float* b2  = (const float*)d_in[5];
    float*       out = (float*)d_out;

    const int N = in_sizes[0] / IN_DIM;
    int G = out_size / IN_DIM;
    if (G > G_MAX) G = G_MAX;

    seg_offsets_kernel<<<(N + 1 + 255) / 256, 256>>>(b32, N, G);

    cudaFuncSetAttribute(attn_pool_kernel,
                         cudaFuncAttributeMaxDynamicSharedMemorySize, SMEM_TOTAL);
    attn_pool_kernel<<<G, THREADS, SMEM_TOTAL>>>(x, W1, b1, W2, b2, out);
}

// round 17
// speedup vs baseline: 1.0621x; 1.0556x over previous
#include <cuda_runtime.h>
#include <cuda_fp16.h>
#include <cstdint>
#include <math_constants.h>

#define IN_DIM   128
#define HID      64
#define G_MAX    8192
#define CHUNK    64
#define THREADS  256
#define KP       136        // fp16 row stride: 272 B = 17*16B -> ldmatrix conflict-free
#define MT_STRIDE (16 * KP * 2)   // 4352 B per 16-row tile group
#define XBUF_SZ  17408      // one x buffer: [64 nodes][KP] fp16

// ---- SMEM layout (bytes); tile bases 16B-aligned
#define WH_OFF    0                         // W1^T fp16 [64 n][KP] = 17408
#define XB_OFF    17408                     // x bufs: [buf][64][KP] fp16, x2
#define B1S_OFF   52224                     // 64 f32
#define W2S_OFF   52480                     // 64 f32
#define GP_OFF    52736                     // 2*64 f32 gate partials
#define ES_OFF    53248                     // 64 f32 exp weights
#define ACC2_OFF  53504                     // 3*128 f32 pool quarter-combine
#define RED_OFF   55040                     // 4 f32 (+pad)
#define SMEM_TOTAL 55072                    // x4 CTA = 220.3 KB <= 227 KB/SM

__device__ int g_seg_start[G_MAX + 1];

// ---------------------------------------------------------------------------
// Kernel 1: segment offsets from sorted batch (int32 view; inline i64 detect).
// ---------------------------------------------------------------------------
__global__ void seg_offsets_kernel(const int* __restrict__ b32, int n, int G)
{
    int i = blockIdx.x * blockDim.x + threadIdx.x;
    if (i > n) return;
    const int s = (b32[(n / 2) | 1] == 0) ? 2 : 1;   // int64 -> stride 2 (low word)
    int cur  = (i < n) ? b32[(size_t)i * s]       : G;
    int prev = (i > 0) ? b32[(size_t)(i - 1) * s] : -1;
    cur  = min(max(cur,  -1), G);
    prev = min(max(prev, -1), G);
    for (int g = prev + 1; g <= cur; ++g)
        g_seg_start[g] = i;
}

// ---------------------------------------------------------------------------
// baseline-feature tensor ops (sm_80+, legal at compute_103)
// ---------------------------------------------------------------------------
__device__ __forceinline__ uint32_t smem_u32(const void* p)
{
    uint32_t a;
    asm("{ .reg .u64 t; cvta.to.shared.u64 t, %1; cvt.u32.u64 %0, t; }"
        : "=r"(a) : "l"(p));
    return a;
}

__device__ __forceinline__ void ldmx4(uint32_t addr, uint32_t* r)
{
    asm volatile("ldmatrix.sync.aligned.m8n8.x4.shared.b16 {%0,%1,%2,%3}, [%4];"
                 : "=r"(r[0]), "=r"(r[1]), "=r"(r[2]), "=r"(r[3]) : "r"(addr));
}

__device__ __forceinline__ void mma16816(float* c, const uint32_t* a,
                                         const uint32_t* b)
{
    asm volatile("mma.sync.aligned.m16n8k16.row.col.f32.f16.f16.f32 "
                 "{%0,%1,%2,%3}, {%4,%5,%6,%7}, {%8,%9}, {%0,%1,%2,%3};"
                 : "+f"(c[0]), "+f"(c[1]), "+f"(c[2]), "+f"(c[3])
                 : "r"(a[0]), "r"(a[1]), "r"(a[2]), "r"(a[3]),
                   "r"(b[0]), "r"(b[1]));
}

__device__ __forceinline__ uint32_t pack_h2(float v0, float v1)
{
    const __half h0 = __float2half_rn(v0);
    const __half h1 = __float2half_rn(v1);
    return ((uint32_t)__half_as_ushort(h1) << 16) |
            (uint32_t)__half_as_ushort(h0);
}

// ---------------------------------------------------------------------------
// Kernel 2: fused gate-MLP (mma.sync fp16) + online softmax (2 barriers) +
// pooling; chunk-pipelined via double buffer with direct LDG->STS staging.
// One CTA per graph, 256 threads (8 warps), 4 CTAs/SM (64 regs/thread).
// Warp (mg 0..3, nq 0..1): nodes 16mg..16mg+15 (m16 tile) x hid 32nq..+31.
// ---------------------------------------------------------------------------
__global__ __launch_bounds__(THREADS, 4)
void attn_pool_kernel(const float* __restrict__ x,
                      const float* __restrict__ W1,
                      const float* __restrict__ b1,
                      const float* __restrict__ W2,
                      const float* __restrict__ b2,
                      float* __restrict__ out)
{
    extern __shared__ char smem[];
    float* b1s  = (float*)(smem + B1S_OFF);
    float* w2s  = (float*)(smem + W2S_OFF);
    float* gps  = (float*)(smem + GP_OFF);
    float* es   = (float*)(smem + ES_OFF);
    float* acc2 = (float*)(smem + ACC2_OFF);
    float* red  = (float*)(smem + RED_OFF);

    const uint32_t sb = smem_u32(smem);

    const int tid  = threadIdx.x;
    const int lane = tid & 31;
    const int wid  = tid >> 5;        // 0..7
    const int mg   = wid & 3;         // m-group: nodes 16mg..16mg+15
    const int nq   = wid >> 2;        // hid half: 32nq..32nq+31
    const int g    = blockIdx.x;

    const int start = g_seg_start[g];
    const int end   = g_seg_start[g + 1];

    // ---- stage W1^T fp16 [n][k] (one-time; col-major B fragment layout)
    for (int e = tid; e < HID * IN_DIM; e += THREADS) {
        const int n = e & (HID - 1);
        const int k = e >> 6;
        *(__half*)(smem + WH_OFF + (n * KP + k) * 2) =
            __float2half_rn(W1[k * HID + n]);
    }
    if (tid < HID) { b1s[tid] = b1[tid]; w2s[tid] = W2[tid]; }
    const float b2v = b2[0];

    // ---- ldmatrix per-lane offsets (fragment math validated R9-R16)
    const uint32_t a_off = (((uint32_t)(lane & 15)) * KP +
                            ((uint32_t)(lane >> 4)) * 8) * 2 +
                           (uint32_t)(mg * 16) * KP * 2;
    const uint32_t b_off = (((uint32_t)((lane & 7) + ((lane >> 4) << 3))) * KP +
                            ((uint32_t)((lane >> 3) & 1)) * 8) * 2;
    const uint32_t bw = sb + WH_OFF + (uint32_t)(nq * 32) * KP * 2 + b_off;

    // load/pool identity: thread = (dp dim-pair 0..63, ph node-quarter 0..3)
    const int dp = tid & 63;
    const int ph = tid >> 6;

    float m_run = -CUDART_INF_F;
    float s_run = 0.f;
    float pacc0 = 0.f, pacc1 = 0.f;

    // ---- prologue: stage chunk 0 into buffer 0 (zero-pad tail)
    if (start < end) {
        const int c0 = min(CHUNK, end - start);
        #pragma unroll 8
        for (int i = 0; i < 16; ++i) {
            const int n = ph * 16 + i;
            float2 v = make_float2(0.f, 0.f);
            if (n < c0)
                v = *((const float2*)(x + (size_t)(start + n) * IN_DIM) + dp);
            *(uint32_t*)(smem + XB_OFF + n * (KP * 2) + dp * 4) = pack_h2(v.x, v.y);
        }
    }
    __syncthreads();

    for (int cs = start, p = 0; cs < end; cs += CHUNK, p ^= 1) {
        const int c   = min(CHUNK, end - cs);
        const int cs2 = cs + CHUNK;
        const bool hn = cs2 < end;
        const int c2  = hn ? min(CHUNK, end - cs2) : 0;

        // ---- MMA: warp computes D[16 x 32] = x[16 x 128] @ W1[128 x 32]
        {
            const uint32_t ax = sb + XB_OFF + (uint32_t)p * XBUF_SZ + a_off;

            float acc[4][4];
            #pragma unroll
            for (int nt = 0; nt < 4; ++nt)
                #pragma unroll
                for (int q = 0; q < 4; ++q) acc[nt][q] = 0.f;

            #pragma unroll 1
            for (int ks = 0; ks < 8; ++ks) {
                const uint32_t kb = (uint32_t)ks * 32;   // 16 fp16 = 32 B
                uint32_t ah[4], bh[2][4];
                ldmx4(ax + kb, ah);
                #pragma unroll
                for (int np = 0; np < 2; ++np)
                    ldmx4(bw + (uint32_t)np * MT_STRIDE + kb, bh[np]);
                #pragma unroll
                for (int np = 0; np < 2; ++np) {
                    mma16816(acc[2 * np],     ah, bh[np]);
                    mma16816(acc[2 * np + 1], ah, bh[np] + 2);
                }
            }

            // epilogue: relu + W2 partial (this hid half), quad-reduce
            float gp0 = 0.f, gp1 = 0.f;   // rows (lane>>2), (lane>>2)+8
            #pragma unroll
            for (int nt = 0; nt < 4; ++nt) {
                const int j0 = nq * 32 + nt * 8 + (lane & 3) * 2;
                const float bj0 = b1s[j0], bj1 = b1s[j0 + 1];
                const float wj0 = w2s[j0], wj1 = w2s[j0 + 1];
                gp0 = fmaf(fmaxf(acc[nt][0] + bj0, 0.f), wj0, gp0);
                gp0 = fmaf(fmaxf(acc[nt][1] + bj1, 0.f), wj1, gp0);
                gp1 = fmaf(fmaxf(acc[nt][2] + bj0, 0.f), wj0, gp1);
                gp1 = fmaf(fmaxf(acc[nt][3] + bj1, 0.f), wj1, gp1);
            }
            #pragma unroll
            for (int off = 1; off < 4; off <<= 1) {
                gp0 += __shfl_xor_sync(0xffffffffu, gp0, off);
                gp1 += __shfl_xor_sync(0xffffffffu, gp1, off);
            }
            if ((lane & 3) == 0) {
                const int node = mg * 16 + (lane >> 2);
                gps[nq * 64 + node]     = gp0;
                gps[nq * 64 + node + 8] = gp1;
            }
        }
        __syncthreads();   // BAR 1: gps ready; prev pooling/es reads done

        // ---- warps 0-1: per-warp softmax partials (no inner barrier)
        if (tid < CHUNK) {
            const float gate = (tid < c) ? (gps[tid] + gps[64 + tid] + b2v)
                                         : -CUDART_INF_F;
            float mw = gate;
            #pragma unroll
            for (int o = 16; o; o >>= 1)
                mw = fmaxf(mw, __shfl_xor_sync(0xffffffffu, mw, o));
            const float mws = fmaxf(mw, -1e30f);   // all-masked warp -> finite
            const float e = __expf(gate - mws);    // masked: exp(-inf) = 0
            es[tid] = e;
            float sw = e;
            #pragma unroll
            for (int o = 16; o; o >>= 1)
                sw += __shfl_xor_sync(0xffffffffu, sw, o);
            if (lane == 0) { red[2 * wid] = mws; red[2 * wid + 1] = sw; }
        }

        // ---- all threads: stage next chunk directly (LDG -> cvt -> STS);
        // DRAM latency covered by the other 3 resident CTAs' compute.
        if (hn) {
            char* xb = smem + XB_OFF + (p ^ 1) * XBUF_SZ;
            #pragma unroll 8
            for (int i = 0; i < 16; ++i) {
                const int n = ph * 16 + i;
                float2 f = make_float2(0.f, 0.f);
                if (n < c2)
                    f = *((const float2*)(x + (size_t)(cs2 + n) * IN_DIM) + dp);
                *(uint32_t*)(xb + n * (KP * 2) + dp * 4) = pack_h2(f.x, f.y);
            }
        }
        __syncthreads();   // BAR 2: red + es ready; next buffer staged

        // ---- combine the two warp partials analytically (all threads)
        const float m0 = red[0], s0 = red[1], m1 = red[2], s1 = red[3];
        const float m_new = fmaxf(m_run, fmaxf(m0, m1));
        const float resc  = __expf(m_run - m_new);   // first chunk: 0
        const float sc0   = __expf(m0 - m_new);
        const float sc1   = __expf(m1 - m_new);
        s_run = s_run * resc + fmaf(s0, sc0, s1 * sc1);
        m_run = m_new;

        // ---- pooling from buffer p: thread (dp, ph), dims 2dp & 2dp+1;
        // per-half scale folded into one fmaf at the end.
        {
            const float scp = (ph < 2) ? sc0 : sc1;   // node-half scale
            const char* xb = smem + XB_OFF + p * XBUF_SZ;
            float in0 = 0.f, in1 = 0.f;
            #pragma unroll 4
            for (int i = 0; i < 16; ++i) {
                const int n = ph * 16 + i;
                const float ev = es[n];                // warp-broadcast LDS
                const uint32_t h2 = *(const uint32_t*)(xb + n * (KP * 2) + dp * 4);
                const float v0 =
                    __half2float(__ushort_as_half((unsigned short)(h2 & 0xffff)));
                const float v1 =
                    __half2float(__ushort_as_half((unsigned short)(h2 >> 16)));
                in0 = fmaf(ev, v0, in0);
                in1 = fmaf(ev, v1, in1);
            }
            pacc0 = fmaf(scp, in0, pacc0 * resc);
            pacc1 = fmaf(scp, in1, pacc1 * resc);
        }
    }

    // ---- combine node-quarter partials, write out
    __syncthreads();
    if (ph > 0) {
        acc2[(ph - 1) * IN_DIM + 2 * dp]     = pacc0;
        acc2[(ph - 1) * IN_DIM + 2 * dp + 1] = pacc1;
    }
    __syncthreads();
    if (ph == 0) {
        float2 o2 = make_float2(0.f, 0.f);
        if (end > start) {
            float s0 = pacc0, s1 = pacc1;
            #pragma unroll
            for (int q = 0; q < 3; ++q) {
                s0 += acc2[q * IN_DIM + 2 * dp];
                s1 += acc2[q * IN_DIM + 2 * dp + 1];
            }
            o2.x = s0 / s_run;
            o2.y = s1 / s_run;
        }
        *((float2*)(out + (size_t)g * IN_DIM) + dp) = o2;
    }
}

// ---------------------------------------------------------------------------
extern "C" void kernel_launch(void* const* d_in, const int* in_sizes, int n_in,
                              void* d_out, int out_size)
{
    const float* x   = (const float*)d_in[0];
    const int*   b32 = (const int*)d_in[1];   // int32 view: safe for i32/i64
    const float* W1  = (const float*)d_in[2];
    const float* b1  = (const float*)d_in[3];
    const float* W2  = (const float*)d_in[4];
    const float* b2  = (const float*)d_in[5];
    float*       out = (float*)d_out;

    const int N = in_sizes[0] / IN_DIM;
    int G = out_size / IN_DIM;
    if (G > G_MAX) G = G_MAX;

    seg_offsets_kernel<<<(N + 1 + 255) / 256, 256>>>(b32, N, G);

    cudaFuncSetAttribute(attn_pool_kernel,
                         cudaFuncAttributeMaxDynamicSharedMemorySize, SMEM_TOTAL);
    attn_pool_kernel<<<G, THREADS, SMEM_TOTAL>>>(x, W1, b1, W2, b2, out);
}